// round 1
// baseline (speedup 1.0000x reference)
#include <cuda_runtime.h>

#define BATCH      16384
#define MAX_JETS   10
#define MAX_PAIRS  45
#define NF         64
#define NF4        16          // float4 per feature row
#define THREADS    256

__global__ __launch_bounds__(THREADS)
void create_pairs_sum_kernel(const float4* __restrict__ in,     // [BATCH, MAX_JETS, NF4]
                             const int*    __restrict__ dict,   // [MAX_JETS-1, MAX_PAIRS, 2]
                             const int*    __restrict__ jet_num,// [BATCH]
                             float4*       __restrict__ out,    // [BATCH, MAX_PAIRS, NF4]
                             float*        __restrict__ out_num)// [BATCH]
{
    __shared__ float4 s_in[MAX_JETS * NF4];   // 10 KB
    __shared__ int2   s_pair[MAX_PAIRS];      // 360 B

    const int b   = blockIdx.x;
    const int tid = threadIdx.x;

    // Stage this row's input block (160 float4)
    const float4* src = in + (size_t)b * (MAX_JETS * NF4);
    for (int i = tid; i < MAX_JETS * NF4; i += THREADS)
        s_in[i] = src[i];

    const int n = jet_num[b];

    // Stage the 45 index pairs for this jet count (int2-aligned: offsets are 8B multiples)
    if (tid < MAX_PAIRS) {
        const int2* drow = (const int2*)dict + (size_t)(n - 2) * MAX_PAIRS;
        s_pair[tid] = drow[tid];
    }
    __syncthreads();

    // Write 45*16 = 720 float4, contiguous & coalesced per batch row
    float4* dst = out + (size_t)b * (MAX_PAIRS * NF4);
    #pragma unroll
    for (int k = 0; k < (MAX_PAIRS * NF4 + THREADS - 1) / THREADS; k++) {
        const int idx = k * THREADS + tid;
        if (idx < MAX_PAIRS * NF4) {
            const int p = idx >> 4;        // pair index
            const int f = idx & (NF4 - 1); // float4 index within feature row
            const int2 pr = s_pair[p];
            float4 v = make_float4(0.f, 0.f, 0.f, 0.f);
            if (pr.x >= 0) {
                const float4 a = s_in[pr.x * NF4 + f];
                const float4 c = s_in[pr.y * NF4 + f];
                v.x = a.x + c.x;
                v.y = a.y + c.y;
                v.z = a.z + c.z;
                v.w = a.w + c.w;
            }
            dst[idx] = v;
        }
    }

    if (tid == 0)
        out_num[b] = (float)((n * (n - 1)) >> 1);
}

extern "C" void kernel_launch(void* const* d_in, const int* in_sizes, int n_in,
                              void* d_out, int out_size)
{
    const float4* in      = (const float4*)d_in[0];  // inputs  [16384,10,64] f32
    const int*    dict    = (const int*)   d_in[1];  // dict_vals [9,45,2] i32
    const int*    jet_num = (const int*)   d_in[2];  // jet_num [16384] i32

    float* out_base = (float*)d_out;
    float4* out_pairs = (float4*)out_base;                              // [16384,45,64]
    float*  out_num   = out_base + (size_t)BATCH * MAX_PAIRS * NF;      // [16384]

    create_pairs_sum_kernel<<<BATCH, THREADS>>>(in, dict, jet_num, out_pairs, out_num);
}

// round 2
// speedup vs baseline: 1.1862x; 1.1862x over previous
#include <cuda_runtime.h>

#define BATCH      16384
#define MAX_JETS   10
#define MAX_PAIRS  45
#define NF         64
#define NF2        32          // float2 per feature row
#define THREADS    256

template<int N>
__device__ __forceinline__
void row_task(const float2* __restrict__ src, float2* __restrict__ dst, int lane)
{
    // Load the N jets' float2 for this thread's feature column into registers.
    float2 j[N];
    #pragma unroll
    for (int a = 0; a < N; a++)
        j[a] = src[a * NF2 + lane];

    constexpr int NP = N * (N - 1) / 2;

    // Lexicographic pairs (i,k), i<k — matches itertools.combinations(range(N),2).
    int p = 0;
    #pragma unroll
    for (int a = 0; a < N; a++) {
        #pragma unroll
        for (int c = a + 1; c < N; c++) {
            float2 v;
            v.x = j[a].x + j[c].x;
            v.y = j[a].y + j[c].y;
            __stcs(&dst[p * NF2 + lane], v);
            p++;
        }
    }
    // Zero-fill the invalid tail pairs.
    #pragma unroll
    for (int q = NP; q < MAX_PAIRS; q++)
        __stcs(&dst[q * NF2 + lane], make_float2(0.f, 0.f));
}

__global__ __launch_bounds__(THREADS)
void create_pairs_sum_kernel(const float2* __restrict__ in,      // [BATCH, MAX_JETS, NF2]
                             const int*    __restrict__ jet_num, // [BATCH]
                             float2*       __restrict__ out,     // [BATCH, MAX_PAIRS, NF2]
                             float*        __restrict__ out_num) // [BATCH]
{
    const int warp = (blockIdx.x * THREADS + threadIdx.x) >> 5;  // one warp = one row
    const int lane = threadIdx.x & 31;

    const float2* src = in  + (size_t)warp * (MAX_JETS  * NF2);
    float2*       dst = out + (size_t)warp * (MAX_PAIRS * NF2);

    const int n = __ldg(&jet_num[warp]);   // warp-uniform

    switch (n) {
        case 2:  row_task<2> (src, dst, lane); break;
        case 3:  row_task<3> (src, dst, lane); break;
        case 4:  row_task<4> (src, dst, lane); break;
        case 5:  row_task<5> (src, dst, lane); break;
        case 6:  row_task<6> (src, dst, lane); break;
        case 7:  row_task<7> (src, dst, lane); break;
        case 8:  row_task<8> (src, dst, lane); break;
        case 9:  row_task<9> (src, dst, lane); break;
        default: row_task<10>(src, dst, lane); break;
    }

    if (lane == 0)
        out_num[warp] = (float)((n * (n - 1)) >> 1);
}

extern "C" void kernel_launch(void* const* d_in, const int* in_sizes, int n_in,
                              void* d_out, int out_size)
{
    const float2* in      = (const float2*)d_in[0];  // inputs   [16384,10,64] f32
    // d_in[1] = dict_vals — unused (pairs generated analytically, same order)
    const int*    jet_num = (const int*)   d_in[2];  // jet_num  [16384] i32

    float*  out_base  = (float*)d_out;
    float2* out_pairs = (float2*)out_base;                          // [16384,45,64]
    float*  out_num   = out_base + (size_t)BATCH * MAX_PAIRS * NF;  // [16384]

    const int nwarps  = BATCH;                       // one warp per row
    const int nblocks = nwarps * 32 / THREADS;       // 2048
    create_pairs_sum_kernel<<<nblocks, THREADS>>>(in, jet_num, out_pairs, out_num);
}

// round 3
// speedup vs baseline: 1.2174x; 1.0263x over previous
#include <cuda_runtime.h>
#include <utility>

#define BATCH      16384
#define MAX_JETS   10
#define MAX_PAIRS  45
#define NF         64
#define NF4        16          // float4 per feature row
#define THREADS    256
#define NSTORE     23          // ceil(45/2) STG.128 per row

// Compile-time lexicographic pair tables (itertools.combinations order)
__host__ __device__ constexpr int pair_a(int n, int p) {
    int idx = 0;
    for (int a = 0; a < n; a++)
        for (int c = a + 1; c < n; c++) { if (idx == p) return a; idx++; }
    return 0;
}
__host__ __device__ constexpr int pair_c(int n, int p) {
    int idx = 0;
    for (int a = 0; a < n; a++)
        for (int c = a + 1; c < n; c++) { if (idx == p) return c; idx++; }
    return 0;
}

template<int N, int S>
__device__ __forceinline__
void do_store(const float4 (&j)[MAX_JETS], float4* __restrict__ dst,
              int lane, int half)
{
    constexpr int NP = N * (N - 1) / 2;
    constexpr int P0 = 2 * S;
    constexpr int P1 = 2 * S + 1;

    float4 v0 = make_float4(0.f, 0.f, 0.f, 0.f);
    float4 v1 = make_float4(0.f, 0.f, 0.f, 0.f);

    if constexpr (P0 < NP) {
        constexpr int A = pair_a(N, P0), C = pair_c(N, P0);
        v0.x = j[A].x + j[C].x;  v0.y = j[A].y + j[C].y;
        v0.z = j[A].z + j[C].z;  v0.w = j[A].w + j[C].w;
    }
    if constexpr (P1 < NP) {
        constexpr int A = pair_a(N, P1), C = pair_c(N, P1);
        v1.x = j[A].x + j[C].x;  v1.y = j[A].y + j[C].y;
        v1.z = j[A].z + j[C].z;  v1.w = j[A].w + j[C].w;
    }

    const float4 v = half ? v1 : v0;

    if constexpr (S < NSTORE - 1) {
        __stcs(&dst[S * 32 + lane], v);        // full-warp 512B store
    } else {
        if (half == 0)                         // pair 45 doesn't exist
            __stcs(&dst[S * 32 + lane], v);    // half-warp 256B store
    }
}

template<int N, int... S>
__device__ __forceinline__
void emit_stores(const float4 (&j)[MAX_JETS], float4* __restrict__ dst,
                 int lane, int half, std::integer_sequence<int, S...>)
{
    (do_store<N, S>(j, dst, lane, half), ...);
}

template<int N>
__device__ __forceinline__
void row_task(const float4* __restrict__ src, float4* __restrict__ dst, int lane)
{
    const int half = lane >> 4;
    const int col  = lane & 15;     // float4 column (both halves read same cols)

    float4 j[MAX_JETS];
    #pragma unroll
    for (int a = 0; a < N; a++)
        j[a] = src[a * NF4 + col];

    emit_stores<N>(j, dst, lane, half, std::make_integer_sequence<int, NSTORE>{});
}

__global__ __launch_bounds__(THREADS)
void create_pairs_sum_kernel(const float4* __restrict__ in,      // [BATCH, 10, 16]
                             const int*    __restrict__ jet_num, // [BATCH]
                             float4*       __restrict__ out,     // [BATCH, 45, 16]
                             float*        __restrict__ out_num) // [BATCH]
{
    const int warp = (blockIdx.x * THREADS + threadIdx.x) >> 5;  // one warp = one row
    const int lane = threadIdx.x & 31;

    const float4* src = in  + (size_t)warp * (MAX_JETS  * NF4);
    float4*       dst = out + (size_t)warp * (MAX_PAIRS * NF4);

    const int n = __ldg(&jet_num[warp]);   // warp-uniform

    switch (n) {
        case 2:  row_task<2> (src, dst, lane); break;
        case 3:  row_task<3> (src, dst, lane); break;
        case 4:  row_task<4> (src, dst, lane); break;
        case 5:  row_task<5> (src, dst, lane); break;
        case 6:  row_task<6> (src, dst, lane); break;
        case 7:  row_task<7> (src, dst, lane); break;
        case 8:  row_task<8> (src, dst, lane); break;
        case 9:  row_task<9> (src, dst, lane); break;
        default: row_task<10>(src, dst, lane); break;
    }

    if (lane == 0)
        out_num[warp] = (float)((n * (n - 1)) >> 1);
}

extern "C" void kernel_launch(void* const* d_in, const int* in_sizes, int n_in,
                              void* d_out, int out_size)
{
    const float4* in      = (const float4*)d_in[0];  // inputs   [16384,10,64] f32
    // d_in[1] = dict_vals — unused (pairs generated analytically, same order)
    const int*    jet_num = (const int*)   d_in[2];  // jet_num  [16384] i32

    float*  out_base  = (float*)d_out;
    float4* out_pairs = (float4*)out_base;                          // [16384,45,64]
    float*  out_num   = out_base + (size_t)BATCH * MAX_PAIRS * NF;  // [16384]

    const int nblocks = BATCH * 32 / THREADS;        // 2048
    create_pairs_sum_kernel<<<nblocks, THREADS>>>(in, jet_num, out_pairs, out_num);
}